// round 13
// baseline (speedup 1.0000x reference)
#include <cuda_runtime.h>
#include <cuda_fp16.h>
#include <math.h>

#define NN 100000
#define NE 1600000
#define EP (NE + NN)          // edges + self loops
#define HID 64
#define LAYERS 3

#define SCAN_T 512
#define NB1 ((NN + SCAN_T - 1) / SCAN_T)   // 196

// ---------------- scratch (device globals; no allocation allowed) ----------
__device__ float   g_x[NN * HID];    // current features / residual (fp32)
__device__ __half2 g_xlh[NN * 32];   // xl fp16: 64 halves = 128B per node row
__device__ float   g_xr[NN * HID];   // xr fp32
__device__ float   g_dummy[NN * HID];// dummy output for the profiled aggr
__device__ int     g_deg[NN];        // histogram, then scatter cursor
__device__ int     g_off[NN + 1];    // CSR offsets (exclusive scan)
__device__ int     g_srcs[EP];       // CSR: src node per incoming edge
__device__ int     g_aggr[NB1];      // scan block aggregates
__device__ int     g_flag[NB1];      // scan publish flags

__device__ __forceinline__ unsigned smem_u32(const void* p) {
    return (unsigned)__cvta_generic_to_shared(p);
}

// ---------------- 1) input projection -------------------------------------
__global__ void k_proj(const float* __restrict__ coords,
                       const float* __restrict__ Wp,
                       const float* __restrict__ bp) {
    int i = blockIdx.x * blockDim.x + threadIdx.x;
    if (i >= NN * HID) return;
    int n = i >> 6, c = i & 63;
    float c0 = coords[n * 2 + 0];
    float c1 = coords[n * 2 + 1];
    g_x[i] = fmaf(c0, Wp[c], fmaf(c1, Wp[64 + c], bp[c]));
}

// ---------------- 2) CSR build: histogram over destinations ----------------
// g_deg must be zero on entry: zero-init on call 1, k_reset thereafter.
__global__ void k_hist(const int* __restrict__ ei) {
    int e = blockIdx.x * blockDim.x + threadIdx.x;
    if (e >= EP) return;
    int d = (e < NE) ? ei[NE + e] : (e - NE);
    atomicAdd(&g_deg[d], 1);
}

// ---------------- 3) single-pass scan (decoupled lookback) -----------------
// Each block: local scan, publish aggregate+flag, then sum all predecessor
// aggregates (spin until published). 196 blocks, all resident -> no deadlock.
__global__ void k_scanDL() {
    __shared__ int wsum[SCAN_T / 32];
    __shared__ int sprev;
    int t = threadIdx.x, b = blockIdx.x, i = b * SCAN_T + t;
    int lane = t & 31, wid = t >> 5;
    int v = (i < NN) ? g_deg[i] : 0;
    int x = v;
#pragma unroll
    for (int o = 1; o < 32; o <<= 1) {
        int u = __shfl_up_sync(0xffffffffu, x, o);
        if (lane >= o) x += u;
    }
    if (lane == 31) wsum[wid] = x;
    __syncthreads();
    if (wid == 0) {
        int ws = (lane < SCAN_T / 32) ? wsum[lane] : 0;
        int y = ws;
#pragma unroll
        for (int o = 1; o < 16; o <<= 1) {
            int u = __shfl_up_sync(0xffffffffu, y, o);
            if (lane >= o) y += u;
        }
        if (lane < SCAN_T / 32) wsum[lane] = y - ws;   // exclusive warp offs
        if (lane == SCAN_T / 32 - 1) {                 // block total
            g_aggr[b] = y;
            __threadfence();
            *((volatile int*)&g_flag[b]) = 1;
        }
        // lookback over predecessors
        int acc = 0;
        for (int j = lane; j < b; j += 32) {
            while (*((volatile int*)&g_flag[j]) == 0) {}
            acc += *((volatile int*)&g_aggr[j]);
        }
#pragma unroll
        for (int o = 16; o; o >>= 1) acc += __shfl_xor_sync(0xffffffffu, acc, o);
        if (lane == 0) sprev = acc;
    }
    __syncthreads();
    int prev = sprev;
    if (i < NN) {
        int o = x - v + wsum[wid] + prev;
        g_off[i] = o;
        g_deg[i] = o;                          // reuse as scatter cursor
    }
    if (i == 0) g_off[NN] = EP;
}

// ---------------- 4) CSR scatter --------------------------------------------
__global__ void k_scatter(const int* __restrict__ ei) {
    int e = blockIdx.x * blockDim.x + threadIdx.x;
    if (e >= EP) return;
    int s, d;
    if (e < NE) { s = ei[e]; d = ei[NE + e]; }
    else        { s = e - NE; d = s; }
    int pos = atomicAdd(&g_deg[d], 1);
    g_srcs[pos] = s;
}

// ---------------- 5) trailing reset: g_deg + scan flags for next call ------
__global__ void k_reset() {
    int i = blockIdx.x * blockDim.x + threadIdx.x;
    if (i < NN) g_deg[i] = 0;
    if (i < NB1) g_flag[i] = 0;
}

// ---------------- 6) tensor-core GEMM: [xl|xr] = x @ [Wl|Wr] + bias ---------
// mma.m16n8k16 f16 inputs, f32 accumulate (R10 version — best measured).
__global__ __launch_bounds__(256)
void k_gemm(const float* __restrict__ Wl, const float* __restrict__ bl,
            const float* __restrict__ Wr, const float* __restrict__ br) {
    __shared__ __align__(16) __half xsh[128][72];   // stride 144B
    __shared__ __align__(16) __half wsh[64][136];   // stride 272B
    int tid  = threadIdx.x;
    int row0 = blockIdx.x * 128;

    for (int j = tid; j < 64 * 128 / 4; j += 256) {
        int k = j >> 5;
        int c = (j << 2) & 127;
        float4 v = (c < 64) ? *(const float4*)&Wl[k * 64 + c]
                            : *(const float4*)&Wr[k * 64 + (c - 64)];
        __half2* dst = (__half2*)&wsh[k][c];
        dst[0] = __floats2half2_rn(v.x, v.y);
        dst[1] = __floats2half2_rn(v.z, v.w);
    }
    for (int j = tid; j < 128 * 64 / 4; j += 256) {
        int r = j >> 4;
        int c = (j << 2) & 63;
        int row = row0 + r;
        float4 v = (row < NN) ? *(const float4*)&g_x[row * 64 + c]
                              : make_float4(0.f, 0.f, 0.f, 0.f);
        __half2* dst = (__half2*)&xsh[r][c];
        dst[0] = __floats2half2_rn(v.x, v.y);
        dst[1] = __floats2half2_rn(v.z, v.w);
    }
    __syncthreads();

    int wid  = tid >> 5;
    int lane = tid & 31;
    int g    = lane >> 2;
    int tig  = lane & 3;

    unsigned A[4][4];
    {
        int m = lane >> 3, r = lane & 7;
#pragma unroll
        for (int ks = 0; ks < 4; ks++) {
            unsigned addr = smem_u32(&xsh[wid * 16 + (m & 1) * 8 + r]
                                        [ks * 16 + (m >> 1) * 8]);
            asm volatile("ldmatrix.sync.aligned.m8n8.x4.shared.b16 "
                         "{%0,%1,%2,%3}, [%4];"
                         : "=r"(A[ks][0]), "=r"(A[ks][1]),
                           "=r"(A[ks][2]), "=r"(A[ks][3]) : "r"(addr));
        }
    }

#pragma unroll
    for (int nt = 0; nt < 16; nt++) {
        float c0 = 0.f, c1 = 0.f, c2 = 0.f, c3 = 0.f;
#pragma unroll
        for (int ks = 0; ks < 4; ks++) {
            unsigned B0, B1;
            int m = (lane >> 3) & 1, r = lane & 7;
            unsigned addr = smem_u32(&wsh[ks * 16 + m * 8 + r][nt * 8]);
            asm volatile("ldmatrix.sync.aligned.m8n8.x2.trans.shared.b16 "
                         "{%0,%1}, [%2];"
                         : "=r"(B0), "=r"(B1) : "r"(addr));
            asm volatile("mma.sync.aligned.m16n8k16.row.col.f32.f16.f16.f32 "
                         "{%0,%1,%2,%3}, {%4,%5,%6,%7}, {%8,%9}, {%0,%1,%2,%3};"
                         : "+f"(c0), "+f"(c1), "+f"(c2), "+f"(c3)
                         : "r"(A[ks][0]), "r"(A[ks][1]),
                           "r"(A[ks][2]), "r"(A[ks][3]), "r"(B0), "r"(B1));
        }
        int col   = nt * 8 + tig * 2;
        int row_a = row0 + wid * 16 + g;
        int row_b = row_a + 8;
        if (col < 64) {                          // xl -> fp16
            float bx = bl[col], by = bl[col + 1];
            if (row_a < NN)
                g_xlh[row_a * 32 + (col >> 1)] = __floats2half2_rn(c0 + bx, c1 + by);
            if (row_b < NN)
                g_xlh[row_b * 32 + (col >> 1)] = __floats2half2_rn(c2 + bx, c3 + by);
        } else {                                 // xr -> fp32
            int cc = col - 64;
            float bx = br[cc], by = br[cc + 1];
            if (row_a < NN)
                *(float2*)&g_xr[row_a * 64 + cc] = make_float2(c0 + bx, c1 + by);
            if (row_b < NN)
                *(float2*)&g_xr[row_b * 64 + cc] = make_float2(c2 + bx, c3 + by);
        }
    }
}

// ---------------- 7) FUSED: per-dst attention + softmax + ELU + LN ---------
// R10 version (best measured). mode: 0 -> g_x, 1 -> dout, 2 -> g_dummy.
__device__ __forceinline__ float nan2num(float o) {
    if (!isfinite(o)) o = isnan(o) ? 0.f : (o > 0.f ? 1e6f : -1e6f);
    return o;
}

__device__ __forceinline__ float lrelu(float v) {
    return v > 0.f ? v : 0.2f * v;
}

__device__ __forceinline__ float4 ld_xlh(int s, int l) {
    uint2 u = __ldg((const uint2*)&g_xlh[s * 32 + l * 2]);
    __half2 h0 = *(__half2*)&u.x;
    __half2 h1 = *(__half2*)&u.y;
    float2 f0 = __half22float2(h0);
    float2 f1 = __half22float2(h1);
    return make_float4(f0.x, f0.y, f1.x, f1.y);
}

__global__ __launch_bounds__(256)
void k_aggr_ln(const float* __restrict__ att,
               const float* __restrict__ bias_out,
               const float* __restrict__ gamma, const float* __restrict__ beta,
               float* __restrict__ dout, int mode) {
    int w = (blockIdx.x * blockDim.x + threadIdx.x) >> 5;   // node id
    if (w >= NN) return;
    int lane = threadIdx.x & 31;
    int half = lane >> 4;
    int l    = lane & 15;

    int beg = g_off[w], end = g_off[w + 1];
    int s_fb = __ldg(&g_srcs[beg]);

    float4 xr  = *(const float4*)&g_xr[w * 64 + l * 4];
    float4 at4 = *(const float4*)&att[l * 4];

    float4 acc = make_float4(0.f, 0.f, 0.f, 0.f);
    float  dsum = 0.f;

    int iters = (end - beg + 1) >> 1;            // deg >= 1 (self loop)
    for (int k = 0; k < iters; k += 2) {
        int i0 = beg + 2 * k + half;
        int i1 = i0 + 2;
        bool v0 = (i0 < end);
        bool v1 = (i1 < end);
        int  s0 = v0 ? __ldg(&g_srcs[i0]) : s_fb;
        int  s1 = v1 ? __ldg(&g_srcs[i1]) : s_fb;
        float4 a0 = ld_xlh(s0, l);
        float4 a1 = ld_xlh(s1, l);

        float p0 = lrelu(a0.x + xr.x) * at4.x + lrelu(a0.y + xr.y) * at4.y
                 + lrelu(a0.z + xr.z) * at4.z + lrelu(a0.w + xr.w) * at4.w;
        float p1 = lrelu(a1.x + xr.x) * at4.x + lrelu(a1.y + xr.y) * at4.y
                 + lrelu(a1.z + xr.z) * at4.z + lrelu(a1.w + xr.w) * at4.w;
        p0 += __shfl_xor_sync(0xffffffffu, p0, 1, 8);
        p1 += __shfl_xor_sync(0xffffffffu, p1, 1, 8);
        p0 += __shfl_xor_sync(0xffffffffu, p0, 2, 8);
        p1 += __shfl_xor_sync(0xffffffffu, p1, 2, 8);
        p0 += __shfl_xor_sync(0xffffffffu, p0, 4, 8);
        p1 += __shfl_xor_sync(0xffffffffu, p1, 4, 8);
        float ex0 = v0 ? __expf(p0) : 0.f;       // scores O(1): no max shift
        float ex1 = v1 ? __expf(p1) : 0.f;
        acc.x = fmaf(ex0, a0.x, fmaf(ex1, a1.x, acc.x));
        acc.y = fmaf(ex0, a0.y, fmaf(ex1, a1.y, acc.y));
        acc.z = fmaf(ex0, a0.z, fmaf(ex1, a1.z, acc.z));
        acc.w = fmaf(ex0, a0.w, fmaf(ex1, a1.w, acc.w));
        dsum += ex0 + ex1;
    }

    acc.x += __shfl_xor_sync(0xffffffffu, acc.x, 16);
    acc.y += __shfl_xor_sync(0xffffffffu, acc.y, 16);
    acc.z += __shfl_xor_sync(0xffffffffu, acc.z, 16);
    acc.w += __shfl_xor_sync(0xffffffffu, acc.w, 16);
    dsum  += __shfl_xor_sync(0xffffffffu, dsum, 16);

    float inv = 1.f / (dsum + 1e-16f);
    float4 bo = *(const float4*)&bias_out[l * 4];
    float4 rx = *(const float4*)&g_x[w * 64 + l * 4];
    float y0 = acc.x * inv + bo.x;
    float y1 = acc.y * inv + bo.y;
    float y2 = acc.z * inv + bo.z;
    float y3 = acc.w * inv + bo.w;
    y0 = y0 > 0.f ? y0 : expm1f(y0);
    y1 = y1 > 0.f ? y1 : expm1f(y1);
    y2 = y2 > 0.f ? y2 : expm1f(y2);
    y3 = y3 > 0.f ? y3 : expm1f(y3);
    y0 += rx.x; y1 += rx.y; y2 += rx.z; y3 += rx.w;

    float sum = y0 + y1 + y2 + y3;
#pragma unroll
    for (int o = 1; o < 16; o <<= 1)
        sum += __shfl_xor_sync(0xffffffffu, sum, o, 16);
    float mu = sum * (1.f / 64.f);
    float d0 = y0 - mu, d1 = y1 - mu, d2 = y2 - mu, d3 = y3 - mu;
    float vs = d0 * d0 + d1 * d1 + d2 * d2 + d3 * d3;
#pragma unroll
    for (int o = 1; o < 16; o <<= 1)
        vs += __shfl_xor_sync(0xffffffffu, vs, o, 16);
    float r = rsqrtf(vs * (1.f / 64.f) + 1e-5f);

    float4 gm = *(const float4*)&gamma[l * 4];
    float4 bt = *(const float4*)&beta[l * 4];
    float4 o4;
    o4.x = nan2num(fmaf(d0 * r, gm.x, bt.x));
    o4.y = nan2num(fmaf(d1 * r, gm.y, bt.y));
    o4.z = nan2num(fmaf(d2 * r, gm.z, bt.z));
    o4.w = nan2num(fmaf(d3 * r, gm.w, bt.w));

    if (half == 0) {
        float* outp = (mode == 1) ? dout : (mode == 2 ? g_dummy : g_x);
        *(float4*)&outp[w * 64 + l * 4] = o4;
    }
}

// ---------------- host driver ----------------------------------------------
extern "C" void kernel_launch(void* const* d_in, const int* in_sizes, int n_in,
                              void* d_out, int out_size) {
    const float* coords   = (const float*)d_in[0];
    const int*   ei       = (const int*)  d_in[1];   // int32 (JAX x64 disabled)
    const float* Wp       = (const float*)d_in[2];
    const float* bp       = (const float*)d_in[3];
    const float* Wl       = (const float*)d_in[4];
    const float* bl       = (const float*)d_in[5];
    const float* Wr       = (const float*)d_in[6];
    const float* br       = (const float*)d_in[7];
    const float* att      = (const float*)d_in[8];
    const float* bias_out = (const float*)d_in[9];
    const float* gamma    = (const float*)d_in[10];
    const float* beta     = (const float*)d_in[11];
    float*       outp     = (float*)d_out;

    const int TB = 256;
    const int grid_nh = (NN * HID + TB - 1) / TB;    // 25000
    const int grid_gm = (NN + 127) / 128;            // 782
    const int grid_ep = (EP + TB - 1) / TB;          // 6641
    const int grid_nn = (NN + TB - 1) / TB;          // 391
    const int grid_ag = (NN * 32 + TB - 1) / TB;     // 12500 (warp/node)

    // CSR first so launch #4 (the ncu-captured slot) is a representative
    // k_aggr_ln run (dummy output; real CSR gather pattern).
    k_hist<<<grid_ep, TB>>>(ei);
    k_scanDL<<<NB1, SCAN_T>>>();
    k_scatter<<<grid_ep, TB>>>(ei);
    k_aggr_ln<<<grid_ag, TB>>>(att, bias_out, gamma, beta, outp, 2); // profiled
    k_proj<<<grid_nh, TB>>>(coords, Wp, bp);

    for (int i = 0; i < LAYERS; i++) {
        k_gemm<<<grid_gm, TB>>>(Wl + i * HID * HID, bl + i * HID,
                                Wr + i * HID * HID, br + i * HID);
        k_aggr_ln<<<grid_ag, TB>>>(att + i * HID, bias_out + i * HID,
                                   gamma + i * HID, beta + i * HID,
                                   outp, (i == LAYERS - 1) ? 1 : 0);
    }
    k_reset<<<grid_nn, TB>>>();      // zero g_deg + scan flags for next call
}

// round 14
// speedup vs baseline: 1.3284x; 1.3284x over previous
#include <cuda_runtime.h>
#include <cuda_fp16.h>
#include <math.h>

#define NN 100000
#define NE 1600000
#define EP (NE + NN)          // edges + self loops
#define HID 64
#define LAYERS 3

#define SCAN_T 512
#define NB1 ((NN + SCAN_T - 1) / SCAN_T)   // 196

// ---------------- scratch (device globals; no allocation allowed) ----------
__device__ float   g_x[NN * HID];    // current features / residual (fp32)
__device__ __half2 g_xlh[NN * 32];   // xl fp16: 64 halves = 128B per node row
__device__ float   g_xr[NN * HID];   // xr fp32
__device__ int     g_deg[NN];        // histogram, then scatter cursor
__device__ int     g_off[NN + 1];    // CSR offsets (exclusive scan)
__device__ int     g_srcs[EP];       // CSR: src node per incoming edge
__device__ int     g_aggr[NB1];      // scan block aggregates
__device__ int     g_flag[NB1];      // scan publish flags

__device__ __forceinline__ unsigned smem_u32(const void* p) {
    return (unsigned)__cvta_generic_to_shared(p);
}

// ---------------- 1) input projection -------------------------------------
__global__ void k_proj(const float* __restrict__ coords,
                       const float* __restrict__ Wp,
                       const float* __restrict__ bp) {
    int i = blockIdx.x * blockDim.x + threadIdx.x;
    if (i >= NN * HID) return;
    int n = i >> 6, c = i & 63;
    float c0 = coords[n * 2 + 0];
    float c1 = coords[n * 2 + 1];
    g_x[i] = fmaf(c0, Wp[c], fmaf(c1, Wp[64 + c], bp[c]));
}

// ---------------- 2) CSR build: histogram over destinations ----------------
// g_deg must be zero on entry: zero-init on call 1, k_reset thereafter.
__global__ void k_hist(const int* __restrict__ ei) {
    int e = blockIdx.x * blockDim.x + threadIdx.x;
    if (e >= EP) return;
    int d = (e < NE) ? ei[NE + e] : (e - NE);
    atomicAdd(&g_deg[d], 1);
}

// ---------------- 3) single-pass scan (decoupled lookback) -----------------
__global__ void k_scanDL() {
    __shared__ int wsum[SCAN_T / 32];
    __shared__ int sprev;
    int t = threadIdx.x, b = blockIdx.x, i = b * SCAN_T + t;
    int lane = t & 31, wid = t >> 5;
    int v = (i < NN) ? g_deg[i] : 0;
    int x = v;
#pragma unroll
    for (int o = 1; o < 32; o <<= 1) {
        int u = __shfl_up_sync(0xffffffffu, x, o);
        if (lane >= o) x += u;
    }
    if (lane == 31) wsum[wid] = x;
    __syncthreads();
    if (wid == 0) {
        int ws = (lane < SCAN_T / 32) ? wsum[lane] : 0;
        int y = ws;
#pragma unroll
        for (int o = 1; o < 16; o <<= 1) {
            int u = __shfl_up_sync(0xffffffffu, y, o);
            if (lane >= o) y += u;
        }
        if (lane < SCAN_T / 32) wsum[lane] = y - ws;   // exclusive warp offs
        if (lane == SCAN_T / 32 - 1) {                 // block total
            g_aggr[b] = y;
            __threadfence();
            *((volatile int*)&g_flag[b]) = 1;
        }
        int acc = 0;
        for (int j = lane; j < b; j += 32) {
            while (*((volatile int*)&g_flag[j]) == 0) {}
            acc += *((volatile int*)&g_aggr[j]);
        }
#pragma unroll
        for (int o = 16; o; o >>= 1) acc += __shfl_xor_sync(0xffffffffu, acc, o);
        if (lane == 0) sprev = acc;
    }
    __syncthreads();
    int prev = sprev;
    if (i < NN) {
        int o = x - v + wsum[wid] + prev;
        g_off[i] = o;
        g_deg[i] = o;                          // reuse as scatter cursor
    }
    if (i == 0) g_off[NN] = EP;
}

// ---------------- 4) CSR scatter --------------------------------------------
__global__ void k_scatter(const int* __restrict__ ei) {
    int e = blockIdx.x * blockDim.x + threadIdx.x;
    if (e >= EP) return;
    int s, d;
    if (e < NE) { s = ei[e]; d = ei[NE + e]; }
    else        { s = e - NE; d = s; }
    int pos = atomicAdd(&g_deg[d], 1);
    g_srcs[pos] = s;
}

// ---------------- 5) trailing reset: g_deg + scan flags for next call ------
__global__ void k_reset() {
    int i = blockIdx.x * blockDim.x + threadIdx.x;
    if (i < NN) g_deg[i] = 0;
    if (i < NB1) g_flag[i] = 0;
}

// ---------------- 6) tensor-core GEMM: [xl|xr] = x @ [Wl|Wr] + bias ---------
// mma.m16n8k16 f16 inputs, f32 accumulate (R10 version — best measured).
__global__ __launch_bounds__(256)
void k_gemm(const float* __restrict__ Wl, const float* __restrict__ bl,
            const float* __restrict__ Wr, const float* __restrict__ br) {
    __shared__ __align__(16) __half xsh[128][72];   // stride 144B
    __shared__ __align__(16) __half wsh[64][136];   // stride 272B
    int tid  = threadIdx.x;
    int row0 = blockIdx.x * 128;

    for (int j = tid; j < 64 * 128 / 4; j += 256) {
        int k = j >> 5;
        int c = (j << 2) & 127;
        float4 v = (c < 64) ? *(const float4*)&Wl[k * 64 + c]
                            : *(const float4*)&Wr[k * 64 + (c - 64)];
        __half2* dst = (__half2*)&wsh[k][c];
        dst[0] = __floats2half2_rn(v.x, v.y);
        dst[1] = __floats2half2_rn(v.z, v.w);
    }
    for (int j = tid; j < 128 * 64 / 4; j += 256) {
        int r = j >> 4;
        int c = (j << 2) & 63;
        int row = row0 + r;
        float4 v = (row < NN) ? *(const float4*)&g_x[row * 64 + c]
                              : make_float4(0.f, 0.f, 0.f, 0.f);
        __half2* dst = (__half2*)&xsh[r][c];
        dst[0] = __floats2half2_rn(v.x, v.y);
        dst[1] = __floats2half2_rn(v.z, v.w);
    }
    __syncthreads();

    int wid  = tid >> 5;
    int lane = tid & 31;
    int g    = lane >> 2;
    int tig  = lane & 3;

    unsigned A[4][4];
    {
        int m = lane >> 3, r = lane & 7;
#pragma unroll
        for (int ks = 0; ks < 4; ks++) {
            unsigned addr = smem_u32(&xsh[wid * 16 + (m & 1) * 8 + r]
                                        [ks * 16 + (m >> 1) * 8]);
            asm volatile("ldmatrix.sync.aligned.m8n8.x4.shared.b16 "
                         "{%0,%1,%2,%3}, [%4];"
                         : "=r"(A[ks][0]), "=r"(A[ks][1]),
                           "=r"(A[ks][2]), "=r"(A[ks][3]) : "r"(addr));
        }
    }

#pragma unroll
    for (int nt = 0; nt < 16; nt++) {
        float c0 = 0.f, c1 = 0.f, c2 = 0.f, c3 = 0.f;
#pragma unroll
        for (int ks = 0; ks < 4; ks++) {
            unsigned B0, B1;
            int m = (lane >> 3) & 1, r = lane & 7;
            unsigned addr = smem_u32(&wsh[ks * 16 + m * 8 + r][nt * 8]);
            asm volatile("ldmatrix.sync.aligned.m8n8.x2.trans.shared.b16 "
                         "{%0,%1}, [%2];"
                         : "=r"(B0), "=r"(B1) : "r"(addr));
            asm volatile("mma.sync.aligned.m16n8k16.row.col.f32.f16.f16.f32 "
                         "{%0,%1,%2,%3}, {%4,%5,%6,%7}, {%8,%9}, {%0,%1,%2,%3};"
                         : "+f"(c0), "+f"(c1), "+f"(c2), "+f"(c3)
                         : "r"(A[ks][0]), "r"(A[ks][1]),
                           "r"(A[ks][2]), "r"(A[ks][3]), "r"(B0), "r"(B1));
        }
        int col   = nt * 8 + tig * 2;
        int row_a = row0 + wid * 16 + g;
        int row_b = row_a + 8;
        if (col < 64) {                          // xl -> fp16
            float bx = bl[col], by = bl[col + 1];
            if (row_a < NN)
                g_xlh[row_a * 32 + (col >> 1)] = __floats2half2_rn(c0 + bx, c1 + by);
            if (row_b < NN)
                g_xlh[row_b * 32 + (col >> 1)] = __floats2half2_rn(c2 + bx, c3 + by);
        } else {                                 // xr -> fp32
            int cc = col - 64;
            float bx = br[cc], by = br[cc + 1];
            if (row_a < NN)
                *(float2*)&g_xr[row_a * 64 + cc] = make_float2(c0 + bx, c1 + by);
            if (row_b < NN)
                *(float2*)&g_xr[row_b * 64 + cc] = make_float2(c2 + bx, c3 + by);
        }
    }
}

// ---------------- 7) FUSED: per-dst attention + softmax + ELU + LN ---------
// Issue-bound kernel: score math in half2 (2 dims/instr), predication-free
// main loop (deg>>2 full iterations) + one predicated tail iteration.
__device__ __forceinline__ float nan2num(float o) {
    if (!isfinite(o)) o = isnan(o) ? 0.f : (o > 0.f ? 1e6f : -1e6f);
    return o;
}

__global__ __launch_bounds__(256)
void k_aggr_ln(const float* __restrict__ att,
               const float* __restrict__ bias_out,
               const float* __restrict__ gamma, const float* __restrict__ beta,
               float* __restrict__ dout, int to_dout) {
    int w = (blockIdx.x * blockDim.x + threadIdx.x) >> 5;   // node id
    if (w >= NN) return;
    int lane = threadIdx.x & 31;
    int half = lane >> 4;
    int l    = lane & 15;

    int beg = g_off[w], end = g_off[w + 1];
    int deg = end - beg;

    float4 xrf = *(const float4*)&g_xr[w * 64 + l * 4];
    float4 atf = *(const float4*)&att[l * 4];
    __half2 xr0 = __floats2half2_rn(xrf.x, xrf.y);
    __half2 xr1 = __floats2half2_rn(xrf.z, xrf.w);
    __half2 at0 = __floats2half2_rn(atf.x, atf.y);
    __half2 at1 = __floats2half2_rn(atf.z, atf.w);
    const __half2 k02 = __floats2half2_rn(0.2f, 0.2f);

    float4 acc = make_float4(0.f, 0.f, 0.f, 0.f);
    float  dsum = 0.f;

    const __half2* xlh = g_xlh;

    int nfull = deg >> 2;                         // full 4-edge iterations
    for (int j = 0; j < nfull; j++) {
        int i0 = beg + 4 * j + half;
        int s0 = __ldg(&g_srcs[i0]);
        int s1 = __ldg(&g_srcs[i0 + 2]);
        uint2 u0 = __ldg((const uint2*)&xlh[s0 * 32 + l * 2]);
        uint2 u1 = __ldg((const uint2*)&xlh[s1 * 32 + l * 2]);
        __half2 a00 = *(__half2*)&u0.x, a01 = *(__half2*)&u0.y;
        __half2 a10 = *(__half2*)&u1.x, a11 = *(__half2*)&u1.y;

        __half2 t00 = __hadd2(a00, xr0), t01 = __hadd2(a01, xr1);
        __half2 t10 = __hadd2(a10, xr0), t11 = __hadd2(a11, xr1);
        __half2 l00 = __hmax2(t00, __hmul2(t00, k02));
        __half2 l01 = __hmax2(t01, __hmul2(t01, k02));
        __half2 l10 = __hmax2(t10, __hmul2(t10, k02));
        __half2 l11 = __hmax2(t11, __hmul2(t11, k02));
        __half2 p20 = __hfma2(l00, at0, __hmul2(l01, at1));
        __half2 p21 = __hfma2(l10, at0, __hmul2(l11, at1));
        float p0 = __low2float(p20) + __high2float(p20);
        float p1 = __low2float(p21) + __high2float(p21);

        p0 += __shfl_xor_sync(0xffffffffu, p0, 1, 8);
        p1 += __shfl_xor_sync(0xffffffffu, p1, 1, 8);
        p0 += __shfl_xor_sync(0xffffffffu, p0, 2, 8);
        p1 += __shfl_xor_sync(0xffffffffu, p1, 2, 8);
        p0 += __shfl_xor_sync(0xffffffffu, p0, 4, 8);
        p1 += __shfl_xor_sync(0xffffffffu, p1, 4, 8);
        float ex0 = __expf(p0);                  // scores O(1): no max shift
        float ex1 = __expf(p1);

        float2 f00 = __half22float2(a00), f01 = __half22float2(a01);
        float2 f10 = __half22float2(a10), f11 = __half22float2(a11);
        acc.x = fmaf(ex0, f00.x, fmaf(ex1, f10.x, acc.x));
        acc.y = fmaf(ex0, f00.y, fmaf(ex1, f10.y, acc.y));
        acc.z = fmaf(ex0, f01.x, fmaf(ex1, f11.x, acc.z));
        acc.w = fmaf(ex0, f01.y, fmaf(ex1, f11.y, acc.w));
        dsum += ex0 + ex1;
    }

    if (deg & 3) {                                // predicated tail (1 iter)
        int i0 = beg + 4 * nfull + half;
        int i1 = i0 + 2;
        bool v0 = (i0 < end);
        bool v1 = (i1 < end);
        int s_fb = __ldg(&g_srcs[beg]);
        int s0 = v0 ? __ldg(&g_srcs[i0]) : s_fb;
        int s1 = v1 ? __ldg(&g_srcs[i1]) : s_fb;
        uint2 u0 = __ldg((const uint2*)&xlh[s0 * 32 + l * 2]);
        uint2 u1 = __ldg((const uint2*)&xlh[s1 * 32 + l * 2]);
        __half2 a00 = *(__half2*)&u0.x, a01 = *(__half2*)&u0.y;
        __half2 a10 = *(__half2*)&u1.x, a11 = *(__half2*)&u1.y;

        __half2 t00 = __hadd2(a00, xr0), t01 = __hadd2(a01, xr1);
        __half2 t10 = __hadd2(a10, xr0), t11 = __hadd2(a11, xr1);
        __half2 l00 = __hmax2(t00, __hmul2(t00, k02));
        __half2 l01 = __hmax2(t01, __hmul2(t01, k02));
        __half2 l10 = __hmax2(t10, __hmul2(t10, k02));
        __half2 l11 = __hmax2(t11, __hmul2(t11, k02));
        __half2 p20 = __hfma2(l00, at0, __hmul2(l01, at1));
        __half2 p21 = __hfma2(l10, at0, __hmul2(l11, at1));
        float p0 = __low2float(p20) + __high2float(p20);
        float p1 = __low2float(p21) + __high2float(p21);

        p0 += __shfl_xor_sync(0xffffffffu, p0, 1, 8);
        p1 += __shfl_xor_sync(0xffffffffu, p1, 1, 8);
        p0 += __shfl_xor_sync(0xffffffffu, p0, 2, 8);
        p1 += __shfl_xor_sync(0xffffffffu, p1, 2, 8);
        p0 += __shfl_xor_sync(0xffffffffu, p0, 4, 8);
        p1 += __shfl_xor_sync(0xffffffffu, p1, 4, 8);
        float ex0 = v0 ? __expf(p0) : 0.f;
        float ex1 = v1 ? __expf(p1) : 0.f;

        float2 f00 = __half22float2(a00), f01 = __half22float2(a01);
        float2 f10 = __half22float2(a10), f11 = __half22float2(a11);
        acc.x = fmaf(ex0, f00.x, fmaf(ex1, f10.x, acc.x));
        acc.y = fmaf(ex0, f00.y, fmaf(ex1, f10.y, acc.y));
        acc.z = fmaf(ex0, f01.x, fmaf(ex1, f11.x, acc.z));
        acc.w = fmaf(ex0, f01.y, fmaf(ex1, f11.y, acc.w));
        dsum += ex0 + ex1;
    }

    // combine halves (xor 16 symmetric)
    acc.x += __shfl_xor_sync(0xffffffffu, acc.x, 16);
    acc.y += __shfl_xor_sync(0xffffffffu, acc.y, 16);
    acc.z += __shfl_xor_sync(0xffffffffu, acc.z, 16);
    acc.w += __shfl_xor_sync(0xffffffffu, acc.w, 16);
    dsum  += __shfl_xor_sync(0xffffffffu, dsum, 16);

    float inv = 1.f / (dsum + 1e-16f);
    float4 bo = *(const float4*)&bias_out[l * 4];
    float4 rx = *(const float4*)&g_x[w * 64 + l * 4];
    float y0 = acc.x * inv + bo.x;
    float y1 = acc.y * inv + bo.y;
    float y2 = acc.z * inv + bo.z;
    float y3 = acc.w * inv + bo.w;
    y0 = y0 > 0.f ? y0 : expm1f(y0);
    y1 = y1 > 0.f ? y1 : expm1f(y1);
    y2 = y2 > 0.f ? y2 : expm1f(y2);
    y3 = y3 > 0.f ? y3 : expm1f(y3);
    y0 += rx.x; y1 += rx.y; y2 += rx.z; y3 += rx.w;

    float sum = y0 + y1 + y2 + y3;
#pragma unroll
    for (int o = 1; o < 16; o <<= 1)
        sum += __shfl_xor_sync(0xffffffffu, sum, o, 16);
    float mu = sum * (1.f / 64.f);
    float d0 = y0 - mu, d1 = y1 - mu, d2 = y2 - mu, d3 = y3 - mu;
    float vs = d0 * d0 + d1 * d1 + d2 * d2 + d3 * d3;
#pragma unroll
    for (int o = 1; o < 16; o <<= 1)
        vs += __shfl_xor_sync(0xffffffffu, vs, o, 16);
    float r = rsqrtf(vs * (1.f / 64.f) + 1e-5f);

    float4 gm = *(const float4*)&gamma[l * 4];
    float4 bt = *(const float4*)&beta[l * 4];
    float4 o4;
    o4.x = nan2num(fmaf(d0 * r, gm.x, bt.x));
    o4.y = nan2num(fmaf(d1 * r, gm.y, bt.y));
    o4.z = nan2num(fmaf(d2 * r, gm.z, bt.z));
    o4.w = nan2num(fmaf(d3 * r, gm.w, bt.w));

    if (half == 0) {
        float* outp = to_dout ? dout : g_x;
        *(float4*)&outp[w * 64 + l * 4] = o4;
    }
}

// ---------------- host driver ----------------------------------------------
extern "C" void kernel_launch(void* const* d_in, const int* in_sizes, int n_in,
                              void* d_out, int out_size) {
    const float* coords   = (const float*)d_in[0];
    const int*   ei       = (const int*)  d_in[1];   // int32 (JAX x64 disabled)
    const float* Wp       = (const float*)d_in[2];
    const float* bp       = (const float*)d_in[3];
    const float* Wl       = (const float*)d_in[4];
    const float* bl       = (const float*)d_in[5];
    const float* Wr       = (const float*)d_in[6];
    const float* br       = (const float*)d_in[7];
    const float* att      = (const float*)d_in[8];
    const float* bias_out = (const float*)d_in[9];
    const float* gamma    = (const float*)d_in[10];
    const float* beta     = (const float*)d_in[11];
    float*       outp     = (float*)d_out;

    const int TB = 256;
    const int grid_nh = (NN * HID + TB - 1) / TB;    // 25000
    const int grid_gm = (NN + 127) / 128;            // 782
    const int grid_ep = (EP + TB - 1) / TB;          // 6641
    const int grid_nn = (NN + TB - 1) / TB;          // 391
    const int grid_ag = (NN * 32 + TB - 1) / TB;     // 12500 (warp/node)

    k_hist<<<grid_ep, TB>>>(ei);
    k_scanDL<<<NB1, SCAN_T>>>();
    k_scatter<<<grid_ep, TB>>>(ei);
    k_proj<<<grid_nh, TB>>>(coords, Wp, bp);

    for (int i = 0; i < LAYERS; i++) {
        k_gemm<<<grid_gm, TB>>>(Wl + i * HID * HID, bl + i * HID,
                                Wr + i * HID * HID, br + i * HID);
        k_aggr_ln<<<grid_ag, TB>>>(att + i * HID, bias_out + i * HID,
                                   gamma + i * HID, beta + i * HID,
                                   outp, (i == LAYERS - 1) ? 1 : 0);
    }
    k_reset<<<grid_nn, TB>>>();      // zero g_deg + scan flags for next call
}

// round 15
// speedup vs baseline: 1.3383x; 1.0075x over previous
#include <cuda_runtime.h>
#include <cuda_fp16.h>
#include <math.h>

#define NN 100000
#define NE 1600000
#define EP (NE + NN)          // edges + self loops
#define HID 64
#define LAYERS 3

#define SCAN_T 512
#define NB1 ((NN + SCAN_T - 1) / SCAN_T)   // 196

// ---------------- scratch (device globals; no allocation allowed) ----------
__device__ float   g_x[NN * HID];    // current features / residual (fp32)
__device__ __half2 g_xlh[NN * 32];   // xl fp16: 64 halves = 128B per node row
__device__ float   g_xr[NN * HID];   // xr fp32
__device__ int     g_deg[NN];        // histogram, then scatter cursor
__device__ int     g_off[NN + 1];    // CSR offsets (exclusive scan)
__device__ int     g_srcs[EP];       // CSR: src node per incoming edge
__device__ int     g_aggr[NB1];      // scan block aggregates
__device__ int     g_flag[NB1];      // scan publish flags

__device__ __forceinline__ unsigned smem_u32(const void* p) {
    return (unsigned)__cvta_generic_to_shared(p);
}

// ---------------- 1) input projection (vectorized: 4 cols/thread) ----------
__global__ void k_proj(const float* __restrict__ coords,
                       const float* __restrict__ Wp,
                       const float* __restrict__ bp) {
    int i = blockIdx.x * blockDim.x + threadIdx.x;
    if (i >= NN * 16) return;
    int n = i >> 4, c4 = (i & 15) << 2;
    float c0 = coords[n * 2 + 0];
    float c1 = coords[n * 2 + 1];
    float4 w0 = *(const float4*)&Wp[c4];
    float4 w1 = *(const float4*)&Wp[64 + c4];
    float4 b  = *(const float4*)&bp[c4];
    float4 o;
    o.x = fmaf(c0, w0.x, fmaf(c1, w1.x, b.x));
    o.y = fmaf(c0, w0.y, fmaf(c1, w1.y, b.y));
    o.z = fmaf(c0, w0.z, fmaf(c1, w1.z, b.z));
    o.w = fmaf(c0, w0.w, fmaf(c1, w1.w, b.w));
    *(float4*)&g_x[n * 64 + c4] = o;
}

// ---------------- 2) CSR build: histogram over destinations ----------------
// g_deg must be zero on entry: zero-init on call 1, k_reset thereafter.
__global__ void k_hist(const int* __restrict__ ei) {
    int e = blockIdx.x * blockDim.x + threadIdx.x;
    if (e >= EP) return;
    int d = (e < NE) ? ei[NE + e] : (e - NE);
    atomicAdd(&g_deg[d], 1);
}

// ---------------- 3) single-pass scan (decoupled lookback) -----------------
__global__ void k_scanDL() {
    __shared__ int wsum[SCAN_T / 32];
    __shared__ int sprev;
    int t = threadIdx.x, b = blockIdx.x, i = b * SCAN_T + t;
    int lane = t & 31, wid = t >> 5;
    int v = (i < NN) ? g_deg[i] : 0;
    int x = v;
#pragma unroll
    for (int o = 1; o < 32; o <<= 1) {
        int u = __shfl_up_sync(0xffffffffu, x, o);
        if (lane >= o) x += u;
    }
    if (lane == 31) wsum[wid] = x;
    __syncthreads();
    if (wid == 0) {
        int ws = (lane < SCAN_T / 32) ? wsum[lane] : 0;
        int y = ws;
#pragma unroll
        for (int o = 1; o < 16; o <<= 1) {
            int u = __shfl_up_sync(0xffffffffu, y, o);
            if (lane >= o) y += u;
        }
        if (lane < SCAN_T / 32) wsum[lane] = y - ws;   // exclusive warp offs
        if (lane == SCAN_T / 32 - 1) {                 // block total
            g_aggr[b] = y;
            __threadfence();
            *((volatile int*)&g_flag[b]) = 1;
        }
        int acc = 0;
        for (int j = lane; j < b; j += 32) {
            while (*((volatile int*)&g_flag[j]) == 0) {}
            acc += *((volatile int*)&g_aggr[j]);
        }
#pragma unroll
        for (int o = 16; o; o >>= 1) acc += __shfl_xor_sync(0xffffffffu, acc, o);
        if (lane == 0) sprev = acc;
    }
    __syncthreads();
    int prev = sprev;
    if (i < NN) {
        int o = x - v + wsum[wid] + prev;
        g_off[i] = o;
        g_deg[i] = o;                          // reuse as scatter cursor
    }
    if (i == 0) g_off[NN] = EP;
}

// ---------------- 4) CSR scatter --------------------------------------------
__global__ void k_scatter(const int* __restrict__ ei) {
    int e = blockIdx.x * blockDim.x + threadIdx.x;
    if (e >= EP) return;
    int s, d;
    if (e < NE) { s = ei[e]; d = ei[NE + e]; }
    else        { s = e - NE; d = s; }
    int pos = atomicAdd(&g_deg[d], 1);
    g_srcs[pos] = s;
}

// ---------------- 5) trailing reset: g_deg + scan flags for next call ------
__global__ void k_reset() {
    int i = blockIdx.x * blockDim.x + threadIdx.x;
    if (i < NN) g_deg[i] = 0;
    if (i < NB1) g_flag[i] = 0;
}

// ---------------- 6) tensor-core GEMM: [xl|xr] = x @ [Wl|Wr] + bias ---------
// Warp tiling: 8 warps = 4 row-groups (32 rows) x 2 col-halves (64 cols).
// Each warp: 2 A-tiles, 8 n-tiles; every B fragment feeds 2 mmas (reuse 2x),
// LDSM per warp 68 -> 40, and the fp16/fp32 epilogue branch is warp-uniform.
__global__ __launch_bounds__(256)
void k_gemm(const float* __restrict__ Wl, const float* __restrict__ bl,
            const float* __restrict__ Wr, const float* __restrict__ br) {
    __shared__ __align__(16) __half xsh[128][72];   // stride 144B
    __shared__ __align__(16) __half wsh[64][136];   // stride 272B
    int tid  = threadIdx.x;
    int row0 = blockIdx.x * 128;

    for (int j = tid; j < 64 * 128 / 4; j += 256) {
        int k = j >> 5;
        int c = (j << 2) & 127;
        float4 v = (c < 64) ? *(const float4*)&Wl[k * 64 + c]
                            : *(const float4*)&Wr[k * 64 + (c - 64)];
        __half2* dst = (__half2*)&wsh[k][c];
        dst[0] = __floats2half2_rn(v.x, v.y);
        dst[1] = __floats2half2_rn(v.z, v.w);
    }
    for (int j = tid; j < 128 * 64 / 4; j += 256) {
        int r = j >> 4;
        int c = (j << 2) & 63;
        int row = row0 + r;
        float4 v = (row < NN) ? *(const float4*)&g_x[row * 64 + c]
                              : make_float4(0.f, 0.f, 0.f, 0.f);
        __half2* dst = (__half2*)&xsh[r][c];
        dst[0] = __floats2half2_rn(v.x, v.y);
        dst[1] = __floats2half2_rn(v.z, v.w);
    }
    __syncthreads();

    int wid   = tid >> 5;
    int lane  = tid & 31;
    int rgrp  = wid & 3;             // row group: rows rgrp*32 .. +31
    int chalf = wid >> 2;            // col half: cols chalf*64 .. +63
    int g     = lane >> 2;
    int tig   = lane & 3;
    int m     = lane >> 3, r = lane & 7;
    int bm    = (lane >> 3) & 1, brow = lane & 7;

    // A fragments: 2 m-tiles x 4 k-steps
    unsigned A[2][4][4];
#pragma unroll
    for (int mt = 0; mt < 2; mt++) {
#pragma unroll
        for (int ks = 0; ks < 4; ks++) {
            unsigned addr = smem_u32(&xsh[rgrp * 32 + mt * 16 + (m & 1) * 8 + r]
                                        [ks * 16 + (m >> 1) * 8]);
            asm volatile("ldmatrix.sync.aligned.m8n8.x4.shared.b16 "
                         "{%0,%1,%2,%3}, [%4];"
                         : "=r"(A[mt][ks][0]), "=r"(A[mt][ks][1]),
                           "=r"(A[mt][ks][2]), "=r"(A[mt][ks][3]) : "r"(addr));
        }
    }

#pragma unroll
    for (int ntl = 0; ntl < 8; ntl++) {
        int colbase = chalf * 64 + ntl * 8;
        float c0[2] = {0.f, 0.f}, c1[2] = {0.f, 0.f};
        float c2[2] = {0.f, 0.f}, c3[2] = {0.f, 0.f};
#pragma unroll
        for (int ks = 0; ks < 4; ks++) {
            unsigned B0, B1;
            unsigned addr = smem_u32(&wsh[ks * 16 + bm * 8 + brow][colbase]);
            asm volatile("ldmatrix.sync.aligned.m8n8.x2.trans.shared.b16 "
                         "{%0,%1}, [%2];"
                         : "=r"(B0), "=r"(B1) : "r"(addr));
#pragma unroll
            for (int mt = 0; mt < 2; mt++) {
                asm volatile("mma.sync.aligned.m16n8k16.row.col.f32.f16.f16.f32 "
                             "{%0,%1,%2,%3}, {%4,%5,%6,%7}, {%8,%9}, {%0,%1,%2,%3};"
                             : "+f"(c0[mt]), "+f"(c1[mt]), "+f"(c2[mt]), "+f"(c3[mt])
                             : "r"(A[mt][ks][0]), "r"(A[mt][ks][1]),
                               "r"(A[mt][ks][2]), "r"(A[mt][ks][3]),
                               "r"(B0), "r"(B1));
            }
        }
        int col = colbase + tig * 2;
        if (chalf == 0) {                        // xl -> fp16 (warp-uniform)
            float bx = bl[col], by = bl[col + 1];
#pragma unroll
            for (int mt = 0; mt < 2; mt++) {
                int row_a = row0 + rgrp * 32 + mt * 16 + g;
                int row_b = row_a + 8;
                if (row_a < NN)
                    g_xlh[row_a * 32 + (col >> 1)] =
                        __floats2half2_rn(c0[mt] + bx, c1[mt] + by);
                if (row_b < NN)
                    g_xlh[row_b * 32 + (col >> 1)] =
                        __floats2half2_rn(c2[mt] + bx, c3[mt] + by);
            }
        } else {                                 // xr -> fp32 (warp-uniform)
            int cc = col - 64;
            float bx = br[cc], by = br[cc + 1];
#pragma unroll
            for (int mt = 0; mt < 2; mt++) {
                int row_a = row0 + rgrp * 32 + mt * 16 + g;
                int row_b = row_a + 8;
                if (row_a < NN)
                    *(float2*)&g_xr[row_a * 64 + cc] =
                        make_float2(c0[mt] + bx, c1[mt] + by);
                if (row_b < NN)
                    *(float2*)&g_xr[row_b * 64 + cc] =
                        make_float2(c2[mt] + bx, c3[mt] + by);
            }
        }
    }
}

// ---------------- 7) FUSED: per-dst attention + softmax + ELU + LN ---------
// R14 version (frozen): half2 score math, predication-free main loop.
__device__ __forceinline__ float nan2num(float o) {
    if (!isfinite(o)) o = isnan(o) ? 0.f : (o > 0.f ? 1e6f : -1e6f);
    return o;
}

__global__ __launch_bounds__(256)
void k_aggr_ln(const float* __restrict__ att,
               const float* __restrict__ bias_out,
               const float* __restrict__ gamma, const float* __restrict__ beta,
               float* __restrict__ dout, int to_dout) {
    int w = (blockIdx.x * blockDim.x + threadIdx.x) >> 5;   // node id
    if (w >= NN) return;
    int lane = threadIdx.x & 31;
    int half = lane >> 4;
    int l    = lane & 15;

    int beg = g_off[w], end = g_off[w + 1];
    int deg = end - beg;

    float4 xrf = *(const float4*)&g_xr[w * 64 + l * 4];
    float4 atf = *(const float4*)&att[l * 4];
    __half2 xr0 = __floats2half2_rn(xrf.x, xrf.y);
    __half2 xr1 = __floats2half2_rn(xrf.z, xrf.w);
    __half2 at0 = __floats2half2_rn(atf.x, atf.y);
    __half2 at1 = __floats2half2_rn(atf.z, atf.w);
    const __half2 k02 = __floats2half2_rn(0.2f, 0.2f);

    float4 acc = make_float4(0.f, 0.f, 0.f, 0.f);
    float  dsum = 0.f;

    const __half2* xlh = g_xlh;

    int nfull = deg >> 2;                         // full 4-edge iterations
    for (int j = 0; j < nfull; j++) {
        int i0 = beg + 4 * j + half;
        int s0 = __ldg(&g_srcs[i0]);
        int s1 = __ldg(&g_srcs[i0 + 2]);
        uint2 u0 = __ldg((const uint2*)&xlh[s0 * 32 + l * 2]);
        uint2 u1 = __ldg((const uint2*)&xlh[s1 * 32 + l * 2]);
        __half2 a00 = *(__half2*)&u0.x, a01 = *(__half2*)&u0.y;
        __half2 a10 = *(__half2*)&u1.x, a11 = *(__half2*)&u1.y;

        __half2 t00 = __hadd2(a00, xr0), t01 = __hadd2(a01, xr1);
        __half2 t10 = __hadd2(a10, xr0), t11 = __hadd2(a11, xr1);
        __half2 l00 = __hmax2(t00, __hmul2(t00, k02));
        __half2 l01 = __hmax2(t01, __hmul2(t01, k02));
        __half2 l10 = __hmax2(t10, __hmul2(t10, k02));
        __half2 l11 = __hmax2(t11, __hmul2(t11, k02));
        __half2 p20 = __hfma2(l00, at0, __hmul2(l01, at1));
        __half2 p21 = __hfma2(l10, at0, __hmul2(l11, at1));
        float p0 = __low2float(p20) + __high2float(p20);
        float p1 = __low2float(p21) + __high2float(p21);

        p0 += __shfl_xor_sync(0xffffffffu, p0, 1, 8);
        p1 += __shfl_xor_sync(0xffffffffu, p1, 1, 8);
        p0 += __shfl_xor_sync(0xffffffffu, p0, 2, 8);
        p1 += __shfl_xor_sync(0xffffffffu, p1, 2, 8);
        p0 += __shfl_xor_sync(0xffffffffu, p0, 4, 8);
        p1 += __shfl_xor_sync(0xffffffffu, p1, 4, 8);
        float ex0 = __expf(p0);                  // scores O(1): no max shift
        float ex1 = __expf(p1);

        float2 f00 = __half22float2(a00), f01 = __half22float2(a01);
        float2 f10 = __half22float2(a10), f11 = __half22float2(a11);
        acc.x = fmaf(ex0, f00.x, fmaf(ex1, f10.x, acc.x));
        acc.y = fmaf(ex0, f00.y, fmaf(ex1, f10.y, acc.y));
        acc.z = fmaf(ex0, f01.x, fmaf(ex1, f11.x, acc.z));
        acc.w = fmaf(ex0, f01.y, fmaf(ex1, f11.y, acc.w));
        dsum += ex0 + ex1;
    }

    if (deg & 3) {                                // predicated tail (1 iter)
        int i0 = beg + 4 * nfull + half;
        int i1 = i0 + 2;
        bool v0 = (i0 < end);
        bool v1 = (i1 < end);
        int s_fb = __ldg(&g_srcs[beg]);
        int s0 = v0 ? __ldg(&g_srcs[i0]) : s_fb;
        int s1 = v1 ? __ldg(&g_srcs[i1]) : s_fb;
        uint2 u0 = __ldg((const uint2*)&xlh[s0 * 32 + l * 2]);
        uint2 u1 = __ldg((const uint2*)&xlh[s1 * 32 + l * 2]);
        __half2 a00 = *(__half2*)&u0.x, a01 = *(__half2*)&u0.y;
        __half2 a10 = *(__half2*)&u1.x, a11 = *(__half2*)&u1.y;

        __half2 t00 = __hadd2(a00, xr0), t01 = __hadd2(a01, xr1);
        __half2 t10 = __hadd2(a10, xr0), t11 = __hadd2(a11, xr1);
        __half2 l00 = __hmax2(t00, __hmul2(t00, k02));
        __half2 l01 = __hmax2(t01, __hmul2(t01, k02));
        __half2 l10 = __hmax2(t10, __hmul2(t10, k02));
        __half2 l11 = __hmax2(t11, __hmul2(t11, k02));
        __half2 p20 = __hfma2(l00, at0, __hmul2(l01, at1));
        __half2 p21 = __hfma2(l10, at0, __hmul2(l11, at1));
        float p0 = __low2float(p20) + __high2float(p20);
        float p1 = __low2float(p21) + __high2float(p21);

        p0 += __shfl_xor_sync(0xffffffffu, p0, 1, 8);
        p1 += __shfl_xor_sync(0xffffffffu, p1, 1, 8);
        p0 += __shfl_xor_sync(0xffffffffu, p0, 2, 8);
        p1 += __shfl_xor_sync(0xffffffffu, p1, 2, 8);
        p0 += __shfl_xor_sync(0xffffffffu, p0, 4, 8);
        p1 += __shfl_xor_sync(0xffffffffu, p1, 4, 8);
        float ex0 = v0 ? __expf(p0) : 0.f;
        float ex1 = v1 ? __expf(p1) : 0.f;

        float2 f00 = __half22float2(a00), f01 = __half22float2(a01);
        float2 f10 = __half22float2(a10), f11 = __half22float2(a11);
        acc.x = fmaf(ex0, f00.x, fmaf(ex1, f10.x, acc.x));
        acc.y = fmaf(ex0, f00.y, fmaf(ex1, f10.y, acc.y));
        acc.z = fmaf(ex0, f01.x, fmaf(ex1, f11.x, acc.z));
        acc.w = fmaf(ex0, f01.y, fmaf(ex1, f11.y, acc.w));
        dsum += ex0 + ex1;
    }

    // combine halves (xor 16 symmetric)
    acc.x += __shfl_xor_sync(0xffffffffu, acc.x, 16);
    acc.y += __shfl_xor_sync(0xffffffffu, acc.y, 16);
    acc.z += __shfl_xor_sync(0xffffffffu, acc.z, 16);
    acc.w += __shfl_xor_sync(0xffffffffu, acc.w, 16);
    dsum  += __shfl_xor_sync(0xffffffffu, dsum, 16);

    float inv = 1.f / (dsum + 1e-16f);
    float4 bo = *(const float4*)&bias_out[l * 4];
    float4 rx = *(const float4*)&g_x[w * 64 + l * 4];
    float y0 = acc.x * inv + bo.x;
    float y1 = acc.y * inv + bo.y;
    float y2 = acc.z * inv + bo.z;
    float y3 = acc.w * inv + bo.w;
    y0 = y0 > 0.f ? y0 : expm1f(y0);
    y1 = y1 > 0.f ? y1 : expm1f(y1);
    y2 = y2 > 0.f ? y2 : expm1f(y2);
    y3 = y3 > 0.f ? y3 : expm1f(y3);
    y0 += rx.x; y1 += rx.y; y2 += rx.z; y3 += rx.w;

    float sum = y0 + y1 + y2 + y3;
#pragma unroll
    for (int o = 1; o < 16; o <<= 1)
        sum += __shfl_xor_sync(0xffffffffu, sum, o, 16);
    float mu = sum * (1.f / 64.f);
    float d0 = y0 - mu, d1 = y1 - mu, d2 = y2 - mu, d3 = y3 - mu;
    float vs = d0 * d0 + d1 * d1 + d2 * d2 + d3 * d3;
#pragma unroll
    for (int o = 1; o < 16; o <<= 1)
        vs += __shfl_xor_sync(0xffffffffu, vs, o, 16);
    float r = rsqrtf(vs * (1.f / 64.f) + 1e-5f);

    float4 gm = *(const float4*)&gamma[l * 4];
    float4 bt = *(const float4*)&beta[l * 4];
    float4 o4;
    o4.x = nan2num(fmaf(d0 * r, gm.x, bt.x));
    o4.y = nan2num(fmaf(d1 * r, gm.y, bt.y));
    o4.z = nan2num(fmaf(d2 * r, gm.z, bt.z));
    o4.w = nan2num(fmaf(d3 * r, gm.w, bt.w));

    if (half == 0) {
        float* outp = to_dout ? dout : g_x;
        *(float4*)&outp[w * 64 + l * 4] = o4;
    }
}

// ---------------- host driver ----------------------------------------------
extern "C" void kernel_launch(void* const* d_in, const int* in_sizes, int n_in,
                              void* d_out, int out_size) {
    const float* coords   = (const float*)d_in[0];
    const int*   ei       = (const int*)  d_in[1];   // int32 (JAX x64 disabled)
    const float* Wp       = (const float*)d_in[2];
    const float* bp       = (const float*)d_in[3];
    const float* Wl       = (const float*)d_in[4];
    const float* bl       = (const float*)d_in[5];
    const float* Wr       = (const float*)d_in[6];
    const float* br       = (const float*)d_in[7];
    const float* att      = (const float*)d_in[8];
    const float* bias_out = (const float*)d_in[9];
    const float* gamma    = (const float*)d_in[10];
    const float* beta     = (const float*)d_in[11];
    float*       outp     = (float*)d_out;

    const int TB = 256;
    const int grid_pj = (NN * 16 + TB - 1) / TB;     // 6250
    const int grid_gm = (NN + 127) / 128;            // 782
    const int grid_ep = (EP + TB - 1) / TB;          // 6641
    const int grid_nn = (NN + TB - 1) / TB;          // 391
    const int grid_ag = (NN * 32 + TB - 1) / TB;     // 12500 (warp/node)

    k_hist<<<grid_ep, TB>>>(ei);
    k_scanDL<<<NB1, SCAN_T>>>();
    k_scatter<<<grid_ep, TB>>>(ei);
    k_proj<<<grid_pj, TB>>>(coords, Wp, bp);

    for (int i = 0; i < LAYERS; i++) {
        k_gemm<<<grid_gm, TB>>>(Wl + i * HID * HID, bl + i * HID,
                                Wr + i * HID * HID, br + i * HID);
        k_aggr_ln<<<grid_ag, TB>>>(att + i * HID, bias_out + i * HID,
                                   gamma + i * HID, beta + i * HID,
                                   outp, (i == LAYERS - 1) ? 1 : 0);
    }
    k_reset<<<grid_nn, TB>>>();      // zero g_deg + scan flags for next call
}